// round 5
// baseline (speedup 1.0000x reference)
#include <cuda_runtime.h>
#include <cuda_bf16.h>
#include <mma.h>
#include <cstdint>

using namespace nvcuda;

// Problem shape (fixed): M = B*S = 4096, K = IN = 4096, N = OUT = 4096
#define KDIM 4096
#define NDIM 4096

#define BM 128
#define BN 128
#define BK 32
#define LDS 40      // smem row stride in halves: 80B rows (16B-aligned), padded
#define NTHREADS 256

// Pack two f32 -> two bf16 in one u32, element0 in low 16 bits
__device__ __forceinline__ unsigned pack2_bf16(float a, float b) {
    unsigned ua = (unsigned)__bfloat16_as_ushort(__float2bfloat16(a));
    unsigned ub = (unsigned)__bfloat16_as_ushort(__float2bfloat16(b));
    return ua | (ub << 16);
}
// Dequantize pair: bf16(w) * s in bf16 (matches reference)
__device__ __forceinline__ unsigned pack2_dq(float a, float b, __nv_bfloat16 s) {
    unsigned ua = (unsigned)__bfloat16_as_ushort(__hmul(__float2bfloat16(a), s));
    unsigned ub = (unsigned)__bfloat16_as_ushort(__hmul(__float2bfloat16(b), s));
    return ua | (ub << 16);
}

__global__ void __launch_bounds__(NTHREADS)
wmma_gemm_kernel(const float* __restrict__ x,      // [M, K] f32
                 const float* __restrict__ w,      // [N, K] f32 (fp8-representable)
                 const float* __restrict__ scale,  // [N] f32
                 const float* __restrict__ bias,   // [N] f32
                 float* __restrict__ out,          // [M, N] f32 (bf16-rounded values)
                 int M) {
    __shared__ __align__(16) unsigned char smem_raw[2 * BM * LDS * 2 + 2 * BN * LDS * 2];
    __nv_bfloat16* sA = reinterpret_cast<__nv_bfloat16*>(smem_raw);
    __nv_bfloat16* sB = reinterpret_cast<__nv_bfloat16*>(smem_raw + 2 * BM * LDS * 2);
    const int BUFSZ = BM * LDS;   // halves per buffer

    const int tid  = threadIdx.x;
    const int wid  = tid >> 5;
    const int lane = tid & 31;

    const int m0 = blockIdx.y * BM;
    const int n0 = blockIdx.x * BN;

    // 8 warps: 2 (m) x 4 (n); each warp 64(m) x 32(n) = 4 x 2 wmma tiles of 16x16
    const int warp_m = (wid >> 2) * 64;
    const int warp_n = (wid & 3) * 32;

    wmma::fragment<wmma::accumulator, 16, 16, 16, float> fc[4][2];
#pragma unroll
    for (int mt = 0; mt < 4; mt++)
#pragma unroll
        for (int nt = 0; nt < 2; nt++)
            wmma::fill_fragment(fc[mt][nt], 0.0f);

    const int KTILES = KDIM / BK;   // 128

    // ---- tile staging: 512 chunks of 8 f32 per operand; 2 chunks/thread ----
    float4 pa[4], pb[4];
    float  sc[2];

    auto ld_tile = [&](int kt) {
#pragma unroll
        for (int j = 0; j < 2; j++) {
            int chunk = tid + j * NTHREADS;
            int row = chunk >> 2;
            int g   = chunk & 3;
            const float4* ap = reinterpret_cast<const float4*>(
                x + (size_t)(m0 + row) * KDIM + kt * BK + g * 8);
            pa[2 * j]     = ap[0];
            pa[2 * j + 1] = ap[1];
            const float4* bp = reinterpret_cast<const float4*>(
                w + (size_t)(n0 + row) * KDIM + kt * BK + g * 8);
            pb[2 * j]     = bp[0];
            pb[2 * j + 1] = bp[1];
            sc[j] = scale[n0 + row];
        }
    };
    auto st_tile = [&](int buf) {
#pragma unroll
        for (int j = 0; j < 2; j++) {
            int chunk = tid + j * NTHREADS;
            int row = chunk >> 2;
            int g   = chunk & 3;
            float4 v0 = pa[2 * j], v1 = pa[2 * j + 1];
            uint4 ua;
            ua.x = pack2_bf16(v0.x, v0.y);
            ua.y = pack2_bf16(v0.z, v0.w);
            ua.z = pack2_bf16(v1.x, v1.y);
            ua.w = pack2_bf16(v1.z, v1.w);
            *reinterpret_cast<uint4*>(&sA[buf * BUFSZ + row * LDS + g * 8]) = ua;

            __nv_bfloat16 s = __float2bfloat16(sc[j]);
            float4 w0 = pb[2 * j], w1 = pb[2 * j + 1];
            uint4 ub;
            ub.x = pack2_dq(w0.x, w0.y, s);
            ub.y = pack2_dq(w0.z, w0.w, s);
            ub.z = pack2_dq(w1.x, w1.y, s);
            ub.w = pack2_dq(w1.z, w1.w, s);
            *reinterpret_cast<uint4*>(&sB[buf * BUFSZ + row * LDS + g * 8]) = ub;
        }
    };

    // prologue: stage tile 0 into buffer 0
    ld_tile(0);
    st_tile(0);
    __syncthreads();

    for (int kt = 0; kt < KTILES; kt++) {
        int cur = kt & 1;
        if (kt + 1 < KTILES) ld_tile(kt + 1);   // prefetch to regs

#pragma unroll
        for (int ks = 0; ks < 2; ks++) {
            wmma::fragment<wmma::matrix_a, 16, 16, 16, __nv_bfloat16, wmma::row_major> fa[4];
            wmma::fragment<wmma::matrix_b, 16, 16, 16, __nv_bfloat16, wmma::col_major> fb[2];
#pragma unroll
            for (int mt = 0; mt < 4; mt++)
                wmma::load_matrix_sync(fa[mt],
                    &sA[cur * BUFSZ + (warp_m + mt * 16) * LDS + ks * 16], LDS);
#pragma unroll
            for (int nt = 0; nt < 2; nt++)
                wmma::load_matrix_sync(fb[nt],
                    &sB[cur * BUFSZ + (warp_n + nt * 16) * LDS + ks * 16], LDS);
#pragma unroll
            for (int mt = 0; mt < 4; mt++)
#pragma unroll
                for (int nt = 0; nt < 2; nt++)
                    wmma::mma_sync(fc[mt][nt], fa[mt], fb[nt], fc[mt][nt]);
        }

        if (kt + 1 < KTILES) {
            st_tile(cur ^ 1);       // write next tile to the other buffer
            __syncthreads();
        }
    }
    __syncthreads();   // all warps done with smem tiles -> reuse for epilogue

    // ---- epilogue: stage per-warp 16x16 f32, round to bf16 (+bf16 bias), ----
    // ---- then store the f32 value of that bf16 result (output dtype = f32) ----
    float* epi = reinterpret_cast<float*>(smem_raw) + wid * 256;
#pragma unroll
    for (int mt = 0; mt < 4; mt++) {
#pragma unroll
        for (int nt = 0; nt < 2; nt++) {
            wmma::store_matrix_sync(epi, fc[mt][nt], 16, wmma::mem_row_major);
            __syncwarp();
#pragma unroll
            for (int i = 0; i < 8; i++) {
                int idx = lane + i * 32;
                int row = idx >> 4;
                int col = idx & 15;
                int m = m0 + warp_m + mt * 16 + row;
                int n = n0 + warp_n + nt * 16 + col;
                __nv_bfloat16 v = __hadd(__float2bfloat16(epi[idx]),
                                         __float2bfloat16(bias[n]));
                out[(size_t)m * NDIM + n] = __bfloat162float(v);
            }
            __syncwarp();
        }
    }
}

// ---------------------------------------------------------------------------
// Launch
// ---------------------------------------------------------------------------
extern "C" void kernel_launch(void* const* d_in, const int* in_sizes, int n_in,
                              void* d_out, int out_size) {
    const float* x      = (const float*)d_in[0];   // [B,S,IN] f32
    const float* w_fp8  = (const float*)d_in[1];   // [OUT,IN] f32
    const float* scale  = (const float*)d_in[2];   // [OUT,1] f32
    const float* bias   = (const float*)d_in[3];   // [OUT] f32
    float* out          = (float*)d_out;           // [B,S,OUT] f32 (bf16-rounded)

    int M = in_sizes[0] / KDIM;                    // 4096

    dim3 grid(NDIM / BN, M / BM);
    wmma_gemm_kernel<<<grid, NTHREADS>>>(x, w_fp8, scale, bias, out, M);
}

// round 8
// speedup vs baseline: 2.6938x; 2.6938x over previous
#include <cuda_runtime.h>
#include <cuda_bf16.h>
#include <cstdint>

// Problem shape (fixed): M = B*S = 4096, K = IN = 4096, N = OUT = 4096
#define KDIM 4096
#define NDIM 4096

#define BM 128
#define BN 128
#define BK 64
#define LDA 72      // BK + 8 halves pad -> 144B row stride, conflict-free for ldmatrix
#define NTHREADS 256

// Scratch: converted bf16 operands (device globals, not runtime allocs)
__device__ __nv_bfloat16 g_x_bf16[4096 * KDIM];
__device__ __nv_bfloat16 g_w_bf16[NDIM * KDIM];

// ---------------------------------------------------------------------------
// Preprocess: x (f32) -> bf16 ; w (f32) * scale -> bf16 (bf16 multiply, matches ref)
// ---------------------------------------------------------------------------
__global__ void convert_x_kernel(const float* __restrict__ x, int count4) {
    int i = blockIdx.x * blockDim.x + threadIdx.x;
    if (i >= count4) return;
    float4 v = reinterpret_cast<const float4*>(x)[i];
    __nv_bfloat162 lo = __floats2bfloat162_rn(v.x, v.y);
    __nv_bfloat162 hi = __floats2bfloat162_rn(v.z, v.w);
    uint2 p;
    p.x = *reinterpret_cast<unsigned*>(&lo);
    p.y = *reinterpret_cast<unsigned*>(&hi);
    reinterpret_cast<uint2*>(g_x_bf16)[i] = p;
}

__global__ void convert_w_kernel(const float* __restrict__ w,
                                 const float* __restrict__ scale, int count4) {
    int i = blockIdx.x * blockDim.x + threadIdx.x;
    if (i >= count4) return;
    int o = (i * 4) / KDIM;        // all 4 elems share a row (KDIM % 4 == 0)
    __nv_bfloat16 s = __float2bfloat16(scale[o]);
    float4 v = reinterpret_cast<const float4*>(w)[i];
    __nv_bfloat16 h0 = __hmul(__float2bfloat16(v.x), s);
    __nv_bfloat16 h1 = __hmul(__float2bfloat16(v.y), s);
    __nv_bfloat16 h2 = __hmul(__float2bfloat16(v.z), s);
    __nv_bfloat16 h3 = __hmul(__float2bfloat16(v.w), s);
    __nv_bfloat162 lo = __halves2bfloat162(h0, h1);
    __nv_bfloat162 hi = __halves2bfloat162(h2, h3);
    uint2 p;
    p.x = *reinterpret_cast<unsigned*>(&lo);
    p.y = *reinterpret_cast<unsigned*>(&hi);
    reinterpret_cast<uint2*>(g_w_bf16)[i] = p;
}

// ---------------------------------------------------------------------------
// GEMM: C[M,N] = A[M,K] @ B[N,K]^T, bf16 in / f32 accum / f32 out (bf16-rounded)
// mma.sync m16n8k16, cp.async double-buffered (BK=64), ldmatrix
// ---------------------------------------------------------------------------
__device__ __forceinline__ void cp_async16(void* smem_ptr, const void* gmem_ptr) {
    unsigned saddr = (unsigned)__cvta_generic_to_shared(smem_ptr);
    asm volatile("cp.async.cg.shared.global [%0], [%1], 16;\n" :: "r"(saddr), "l"(gmem_ptr));
}
__device__ __forceinline__ void cp_async_commit() {
    asm volatile("cp.async.commit_group;\n");
}
template <int N>
__device__ __forceinline__ void cp_async_wait() {
    asm volatile("cp.async.wait_group %0;\n" :: "n"(N));
}
__device__ __forceinline__ void ldmatrix_x4(unsigned& r0, unsigned& r1, unsigned& r2,
                                            unsigned& r3, const void* smem_ptr) {
    unsigned saddr = (unsigned)__cvta_generic_to_shared(smem_ptr);
    asm volatile("ldmatrix.sync.aligned.m8n8.x4.shared.b16 {%0,%1,%2,%3}, [%4];\n"
                 : "=r"(r0), "=r"(r1), "=r"(r2), "=r"(r3) : "r"(saddr));
}
__device__ __forceinline__ void mma_16816(float* c, const unsigned* a, const unsigned* b) {
    asm volatile(
        "mma.sync.aligned.m16n8k16.row.col.f32.bf16.bf16.f32 "
        "{%0,%1,%2,%3}, {%4,%5,%6,%7}, {%8,%9}, {%0,%1,%2,%3};\n"
        : "+f"(c[0]), "+f"(c[1]), "+f"(c[2]), "+f"(c[3])
        : "r"(a[0]), "r"(a[1]), "r"(a[2]), "r"(a[3]), "r"(b[0]), "r"(b[1]));
}

#define TILE_HALVES (BM * LDA)                         // 9216 halves per operand tile
#define SMEM_BYTES  (4 * TILE_HALVES * 2)              // 2 bufs x (A+B) = 73728 B

__global__ void __launch_bounds__(NTHREADS, 2)
gemm_bf16_kernel(const float* __restrict__ bias, float* __restrict__ out, int M) {
    extern __shared__ __align__(16) __nv_bfloat16 smem[];
    __nv_bfloat16* sA = smem;                          // [2][BM*LDA]
    __nv_bfloat16* sB = smem + 2 * TILE_HALVES;        // [2][BN*LDA]

    const int tid  = threadIdx.x;
    const int wid  = tid >> 5;
    const int lane = tid & 31;
    const int grp  = lane >> 3;       // 0..3 (ldmatrix address group)
    const int rin  = lane & 7;

    const int m0 = blockIdx.y * BM;
    const int n0 = blockIdx.x * BN;

    // warp tiling: 2 (m) x 4 (n) warps; each warp 64(m) x 32(n)
    const int warp_m = (wid >> 2) * 64;
    const int warp_n = (wid & 3) * 32;

    const __nv_bfloat16* A = g_x_bf16;
    const __nv_bfloat16* B = g_w_bf16;

    float acc[4][4][4];   // [mtile][ntile][frag]
#pragma unroll
    for (int i = 0; i < 4; i++)
#pragma unroll
        for (int j = 0; j < 4; j++)
#pragma unroll
            for (int r = 0; r < 4; r++) acc[i][j][r] = 0.0f;

    const int KTILES = KDIM / BK;   // 64

    // tile loader: 1024 16B chunks per operand tile; 4 chunks/thread each
    auto load_tile = [&](int buf, int kt) {
#pragma unroll
        for (int j = 0; j < 4; j++) {
            int chunk = tid + j * NTHREADS;          // 0..1023
            int row = chunk >> 3;                    // 0..127
            int kc  = chunk & 7;                     // 0..7
            int k   = kt * BK + kc * 8;
            cp_async16(&sA[buf * TILE_HALVES + row * LDA + kc * 8],
                       &A[(size_t)(m0 + row) * KDIM + k]);
            cp_async16(&sB[buf * TILE_HALVES + row * LDA + kc * 8],
                       &B[(size_t)(n0 + row) * KDIM + k]);
        }
    };

    load_tile(0, 0);
    cp_async_commit();

    for (int kt = 0; kt < KTILES; kt++) {
        int cur = kt & 1;
        if (kt + 1 < KTILES) {
            load_tile(cur ^ 1, kt + 1);
            cp_async_commit();
            cp_async_wait<1>();
        } else {
            cp_async_wait<0>();
        }
        __syncthreads();

        const __nv_bfloat16* a_s = &sA[cur * TILE_HALVES];
        const __nv_bfloat16* b_s = &sB[cur * TILE_HALVES];

#pragma unroll
        for (int ks = 0; ks < 4; ks++) {
            const int kbase = ks * 16;

            // A fragments: 4 m-tiles of 16x16 (verified ldmatrix mapping)
            unsigned afrag[4][4];
#pragma unroll
            for (int mt = 0; mt < 4; mt++) {
                int r = warp_m + mt * 16 + (grp & 1) * 8 + rin;
                int c = kbase + (grp >> 1) * 8;
                ldmatrix_x4(afrag[mt][0], afrag[mt][1], afrag[mt][2], afrag[mt][3],
                            &a_s[r * LDA + c]);
            }
            // B fragments: 4 n-tiles of 8(n)x16(k); 2 n-tiles per x4
            unsigned bfrag[4][2];
#pragma unroll
            for (int p = 0; p < 2; p++) {
                int nrow = warp_n + p * 16 + (grp >> 1) * 8 + rin;
                int c = kbase + (grp & 1) * 8;
                ldmatrix_x4(bfrag[2 * p][0], bfrag[2 * p][1],
                            bfrag[2 * p + 1][0], bfrag[2 * p + 1][1],
                            &b_s[nrow * LDA + c]);
            }
#pragma unroll
            for (int mt = 0; mt < 4; mt++)
#pragma unroll
                for (int nt = 0; nt < 4; nt++)
                    mma_16816(acc[mt][nt], afrag[mt], bfrag[nt]);
        }
        __syncthreads();
    }

    // ---- epilogue: bf16-round(acc) + bf16 bias, store f32 (output dtype f32) ----
    const int tig = lane & 3;         // threadID in group of 4
    const int g8  = lane >> 2;        // groupID 0..7
#pragma unroll
    for (int nt = 0; nt < 4; nt++) {
        int n = n0 + warp_n + nt * 8 + tig * 2;
        __nv_bfloat16 bb0 = __float2bfloat16(bias[n]);
        __nv_bfloat16 bb1 = __float2bfloat16(bias[n + 1]);
#pragma unroll
        for (int mt = 0; mt < 4; mt++) {
            int mA = m0 + warp_m + mt * 16 + g8;
            int mB = mA + 8;
            float2 v0, v1;
            v0.x = __bfloat162float(__hadd(__float2bfloat16(acc[mt][nt][0]), bb0));
            v0.y = __bfloat162float(__hadd(__float2bfloat16(acc[mt][nt][1]), bb1));
            v1.x = __bfloat162float(__hadd(__float2bfloat16(acc[mt][nt][2]), bb0));
            v1.y = __bfloat162float(__hadd(__float2bfloat16(acc[mt][nt][3]), bb1));
            *reinterpret_cast<float2*>(&out[(size_t)mA * NDIM + n]) = v0;
            *reinterpret_cast<float2*>(&out[(size_t)mB * NDIM + n]) = v1;
        }
    }
}

// ---------------------------------------------------------------------------
// Launch
// ---------------------------------------------------------------------------
extern "C" void kernel_launch(void* const* d_in, const int* in_sizes, int n_in,
                              void* d_out, int out_size) {
    const float* x     = (const float*)d_in[0];   // [B,S,IN] f32
    const float* w_fp8 = (const float*)d_in[1];   // [OUT,IN] f32
    const float* scale = (const float*)d_in[2];   // [OUT,1] f32
    const float* bias  = (const float*)d_in[3];   // [OUT] f32
    float* out         = (float*)d_out;           // [B,S,OUT] f32 (bf16-rounded values)

    int M = in_sizes[0] / KDIM;                   // 4096

    {
        int c4 = (M * KDIM) / 4;
        convert_x_kernel<<<(c4 + 255) / 256, 256>>>(x, c4);
    }
    {
        int c4 = (NDIM * KDIM) / 4;
        convert_w_kernel<<<(c4 + 255) / 256, 256>>>(w_fp8, scale, c4);
    }
    {
        static bool attr_set = false;
        if (!attr_set) {
            cudaFuncSetAttribute(gemm_bf16_kernel,
                                 cudaFuncAttributeMaxDynamicSharedMemorySize, SMEM_BYTES);
            attr_set = true;
        }
        dim3 grid(NDIM / BN, M / BM);
        gemm_bf16_kernel<<<grid, NTHREADS, SMEM_BYTES>>>(bias, out, M);
    }
}